// round 2
// baseline (speedup 1.0000x reference)
#include <cuda_runtime.h>

#define FDIM 128
#define DEG 16
#define MAXN 65536
#define EPS 1e-12f

// Scratch: per-node inverse L2 norm (allocation-free rule -> __device__ global)
__device__ float g_rn[MAXN];

// ---------------------------------------------------------------------------
// Kernel 1: per-node inverse norm. One warp per node, float4 per lane.
// ---------------------------------------------------------------------------
__global__ void norm_kernel(const float* __restrict__ x, int n) {
    int warp = (blockIdx.x * blockDim.x + threadIdx.x) >> 5;
    int lane = threadIdx.x & 31;
    if (warp >= n) return;
    const float4* xr = reinterpret_cast<const float4*>(x + (size_t)warp * FDIM);
    float4 v = xr[lane];
    float s = v.x * v.x + v.y * v.y + v.z * v.z + v.w * v.w;
#pragma unroll
    for (int o = 16; o; o >>= 1) s += __shfl_xor_sync(0xffffffffu, s, o);
    if (lane == 0) g_rn[warp] = rsqrtf(s + EPS);
}

// ---------------------------------------------------------------------------
// Kernel 2: AGNN. One warp per node. Neighbor rows cached in registers so
// each 512B neighbor row is fetched from L2 exactly once.
// ---------------------------------------------------------------------------
__global__ __launch_bounds__(256, 2) void agnn_kernel(
    const float* __restrict__ x,
    const int*   __restrict__ row_ptr,
    const int*   __restrict__ col_id,
    const float* __restrict__ beta,
    float*       __restrict__ out,
    int n)
{
    int warp = (blockIdx.x * blockDim.x + threadIdx.x) >> 5;
    int lane = threadIdx.x & 31;
    if (warp >= n) return;

    int base = row_ptr[warp];          // fixed degree: base = warp*16, but read CSR for safety
    float b  = beta[0];

    const float4* xi = reinterpret_cast<const float4*>(x + (size_t)warp * FDIM);
    float4 vi = xi[lane];
    float rni = g_rn[warp];

    float4 nb[DEG];
    float  e[DEG];

#pragma unroll
    for (int j = 0; j < DEG; j++) {
        int c = __ldg(&col_id[base + j]);
        const float4* xj = reinterpret_cast<const float4*>(x + (size_t)c * FDIM);
        float4 vj = xj[lane];
        nb[j] = vj;
        float p = vi.x * vj.x + vi.y * vj.y + vi.z * vj.z + vi.w * vj.w;
#pragma unroll
        for (int o = 16; o; o >>= 1) p += __shfl_xor_sync(0xffffffffu, p, o);
        e[j] = b * p * rni * g_rn[c];
    }

    // softmax over the 16 neighbor scores (all lanes hold identical e[])
    float m = -INFINITY;
#pragma unroll
    for (int j = 0; j < DEG; j++) m = fmaxf(m, e[j]);
    float s = 0.0f;
#pragma unroll
    for (int j = 0; j < DEG; j++) { e[j] = __expf(e[j] - m); s += e[j]; }
    float inv = 1.0f / s;

    float4 acc = make_float4(0.f, 0.f, 0.f, 0.f);
#pragma unroll
    for (int j = 0; j < DEG; j++) {
        float a = e[j] * inv;
        acc.x += a * nb[j].x;
        acc.y += a * nb[j].y;
        acc.z += a * nb[j].z;
        acc.w += a * nb[j].w;
    }
    reinterpret_cast<float4*>(out + (size_t)warp * FDIM)[lane] = acc;
}

// ---------------------------------------------------------------------------
// Launch
// ---------------------------------------------------------------------------
extern "C" void kernel_launch(void* const* d_in, const int* in_sizes, int n_in,
                              void* d_out, int out_size) {
    const float* x       = (const float*)d_in[0];
    // d_in[1] = row_id (COO) — not needed with CSR + fixed degree
    const int*   row_ptr = (const int*)d_in[2];
    const int*   col_id  = (const int*)d_in[3];
    const float* beta    = (const float*)d_in[4];
    float*       out     = (float*)d_out;

    int n = in_sizes[2] - 1;   // row_ptr has N+1 entries
    if (n > MAXN) n = MAXN;    // defensive: scratch bound (no-op for this shape)

    int threads = 256;                       // 8 warps = 8 nodes per block
    int blocks  = (n * 32 + threads - 1) / threads;

    norm_kernel<<<blocks, threads>>>(x, n);
    agnn_kernel<<<blocks, threads>>>(x, row_ptr, col_id, beta, out, n);
}

// round 4
// speedup vs baseline: 1.0737x; 1.0737x over previous
#include <cuda_runtime.h>

#define FDIM 128
#define DEG 16
#define MAXN 65536
#define EPS 1e-12f

// Scratch: per-node inverse L2 norm (allocation-free rule -> __device__ global)
__device__ float g_rn[MAXN];

__device__ __forceinline__ float warp_sum(float p) {
#pragma unroll
    for (int o = 16; o; o >>= 1) p += __shfl_xor_sync(0xffffffffu, p, o);
    return p;
}

// ---------------------------------------------------------------------------
// Kernel 1: per-node inverse norm. One warp per node, float4 per lane.
// ---------------------------------------------------------------------------
__global__ void norm_kernel(const float* __restrict__ x, int n) {
    int warp = (blockIdx.x * blockDim.x + threadIdx.x) >> 5;
    int lane = threadIdx.x & 31;
    if (warp >= n) return;
    const float4* xr = reinterpret_cast<const float4*>(x + (size_t)warp * FDIM);
    float4 v = xr[lane];
    float s = warp_sum(v.x * v.x + v.y * v.y + v.z * v.z + v.w * v.w);
    if (lane == 0) g_rn[warp] = rsqrtf(s + EPS);
}

// ---------------------------------------------------------------------------
// Kernel 2: AGNN with ONLINE softmax. One warp per node; single gather per
// neighbor row; no register-resident neighbor cache (occupancy 2x vs R1).
// ---------------------------------------------------------------------------
__global__ __launch_bounds__(256, 4) void agnn_kernel(
    const float* __restrict__ x,
    const int*   __restrict__ row_ptr,
    const int*   __restrict__ col_id,
    const float* __restrict__ beta,
    float*       __restrict__ out,
    int n)
{
    int warp = (blockIdx.x * blockDim.x + threadIdx.x) >> 5;
    int lane = threadIdx.x & 31;
    if (warp >= n) return;

    int base = row_ptr[warp];
    float b  = beta[0];

    const float4* xi = reinterpret_cast<const float4*>(x + (size_t)warp * FDIM);
    float4 vi = xi[lane];
    float rni = g_rn[warp];

    // Preload neighbor indices (uniform across warp; 16 regs)
    int cols[DEG];
#pragma unroll
    for (int j = 0; j < DEG; j++) cols[j] = __ldg(&col_id[base + j]);

    // Online softmax state
    float  m = -INFINITY;
    float  s = 0.0f;
    float4 acc = make_float4(0.f, 0.f, 0.f, 0.f);

#pragma unroll
    for (int j = 0; j < DEG; j++) {
        int c = cols[j];
        const float4* xj = reinterpret_cast<const float4*>(x + (size_t)c * FDIM);
        float4 vj = xj[lane];
        float rnc = __ldg(&g_rn[c]);

        float p = warp_sum(vi.x * vj.x + vi.y * vj.y + vi.z * vj.z + vi.w * vj.w);
        float e = b * p * rni * rnc;

        float mn = fmaxf(m, e);
        float sc = __expf(m - mn);   // 1 when m unchanged; 0 on first iter (m=-inf)
        float w  = __expf(e - mn);
        s = s * sc + w;
        acc.x = acc.x * sc + w * vj.x;
        acc.y = acc.y * sc + w * vj.y;
        acc.z = acc.z * sc + w * vj.z;
        acc.w = acc.w * sc + w * vj.w;
        m = mn;
    }

    float inv = 1.0f / s;
    float4 o = make_float4(acc.x * inv, acc.y * inv, acc.z * inv, acc.w * inv);
    reinterpret_cast<float4*>(out + (size_t)warp * FDIM)[lane] = o;
}

// ---------------------------------------------------------------------------
// Launch
// ---------------------------------------------------------------------------
extern "C" void kernel_launch(void* const* d_in, const int* in_sizes, int n_in,
                              void* d_out, int out_size) {
    const float* x       = (const float*)d_in[0];
    // d_in[1] = row_id (COO) — not needed with CSR + fixed degree
    const int*   row_ptr = (const int*)d_in[2];
    const int*   col_id  = (const int*)d_in[3];
    const float* beta    = (const float*)d_in[4];
    float*       out     = (float*)d_out;

    int n = in_sizes[2] - 1;   // row_ptr has N+1 entries
    if (n > MAXN) n = MAXN;    // defensive: scratch bound (no-op for this shape)

    int threads = 256;                       // 8 warps = 8 nodes per block
    int blocks  = (n * 32 + threads - 1) / threads;

    norm_kernel<<<blocks, threads>>>(x, n);
    agnn_kernel<<<blocks, threads>>>(x, row_ptr, col_id, beta, out, n);
}

// round 5
// speedup vs baseline: 1.3389x; 1.2470x over previous
#include <cuda_runtime.h>

#define FDIM 128
#define DEG 16
#define MAXN 65536
#define EPS 1e-12f

// Scratch: per-node inverse L2 norm (allocation-free rule -> __device__ global)
__device__ float g_rn[MAXN];

__device__ __forceinline__ float warp_sum(float p) {
#pragma unroll
    for (int o = 16; o; o >>= 1) p += __shfl_xor_sync(0xffffffffu, p, o);
    return p;
}

// ---------------------------------------------------------------------------
// Kernel 1: per-node inverse norm. One warp per node, float4 per lane.
// (Also warms L2 with x.)
// ---------------------------------------------------------------------------
__global__ void norm_kernel(const float* __restrict__ x, int n) {
    int warp = (blockIdx.x * blockDim.x + threadIdx.x) >> 5;
    int lane = threadIdx.x & 31;
    if (warp >= n) return;
    const float4* xr = reinterpret_cast<const float4*>(x + (size_t)warp * FDIM);
    float4 v = xr[lane];
    float s = warp_sum(v.x * v.x + v.y * v.y + v.z * v.z + v.w * v.w);
    if (lane == 0) g_rn[warp] = rsqrtf(s + EPS);
}

// ---------------------------------------------------------------------------
// Kernel 2: AGNN, one warp per node. Neighbors processed in PAIRS:
//  - shared butterfly: fold pair partials at offset 16, then 4 shared steps
//  - no max-subtraction: scores are bounded by |beta|, shift by -|beta|
//  - one __expf per lane covers both neighbors of the pair
// ---------------------------------------------------------------------------
__global__ __launch_bounds__(256, 4) void agnn_kernel(
    const float* __restrict__ x,
    const int*   __restrict__ row_ptr,
    const int*   __restrict__ col_id,
    const float* __restrict__ beta,
    float*       __restrict__ out,
    int n)
{
    int warp = (blockIdx.x * blockDim.x + threadIdx.x) >> 5;
    int lane = threadIdx.x & 31;
    if (warp >= n) return;

    int  base = row_ptr[warp];
    float b   = beta[0];
    float babs = fabsf(b);
    bool  hi  = (lane & 16) != 0;

    const float4* xi = reinterpret_cast<const float4*>(x + (size_t)warp * FDIM);
    float4 vi = xi[lane];
    float rni = g_rn[warp];

    // Fold beta * rn_i into the query vector once.
    float kq = b * rni;
    float4 vip = make_float4(vi.x * kq, vi.y * kq, vi.z * kq, vi.w * kq);

    // Preload neighbor indices (uniform across warp)
    int cols[DEG];
#pragma unroll
    for (int j = 0; j < DEG; j++) cols[j] = __ldg(&col_id[base + j]);

    float  s   = 0.0f;
    float4 acc = make_float4(0.f, 0.f, 0.f, 0.f);

#pragma unroll
    for (int j = 0; j < DEG; j += 2) {
        int ca = cols[j];
        int cb = cols[j + 1];
        const float4* xa = reinterpret_cast<const float4*>(x + (size_t)ca * FDIM);
        const float4* xb = reinterpret_cast<const float4*>(x + (size_t)cb * FDIM);
        float4 va = xa[lane];
        float4 vb = xb[lane];
        float rnca = __ldg(&g_rn[ca]);
        float rncb = __ldg(&g_rn[cb]);

        float pa = vip.x * va.x + vip.y * va.y + vip.z * va.z + vip.w * va.w;
        float pb = vip.x * vb.x + vip.y * vb.y + vip.z * vb.z + vip.w * vb.w;

        // Pair fold at offset 16: lanes 0-15 carry pa's partial, 16-31 pb's.
        float keep  = hi ? pb : pa;
        float other = hi ? pa : pb;
        float q = keep + __shfl_xor_sync(0xffffffffu, other, 16);
        // Shared butterfly within each 16-lane half.
        q += __shfl_xor_sync(0xffffffffu, q, 8);
        q += __shfl_xor_sync(0xffffffffu, q, 4);
        q += __shfl_xor_sync(0xffffffffu, q, 2);
        q += __shfl_xor_sync(0xffffffffu, q, 1);

        // Per-half score and exp (one expf per lane serves both neighbors)
        float rnsel = hi ? rncb : rnca;
        float e = fmaf(q, rnsel, -babs);   // e' = beta*cos - |beta|  <= 0
        float w = __expf(e);

        float wa = __shfl_sync(0xffffffffu, w, 0);
        float wb = __shfl_sync(0xffffffffu, w, 16);

        s += wa + wb;
        acc.x += wa * va.x + wb * vb.x;
        acc.y += wa * va.y + wb * vb.y;
        acc.z += wa * va.z + wb * vb.z;
        acc.w += wa * va.w + wb * vb.w;
    }

    float inv = 1.0f / s;
    float4 o = make_float4(acc.x * inv, acc.y * inv, acc.z * inv, acc.w * inv);
    reinterpret_cast<float4*>(out + (size_t)warp * FDIM)[lane] = o;
}

// ---------------------------------------------------------------------------
// Launch
// ---------------------------------------------------------------------------
extern "C" void kernel_launch(void* const* d_in, const int* in_sizes, int n_in,
                              void* d_out, int out_size) {
    const float* x       = (const float*)d_in[0];
    // d_in[1] = row_id (COO) — not needed with CSR + fixed degree
    const int*   row_ptr = (const int*)d_in[2];
    const int*   col_id  = (const int*)d_in[3];
    const float* beta    = (const float*)d_in[4];
    float*       out     = (float*)d_out;

    int n = in_sizes[2] - 1;   // row_ptr has N+1 entries
    if (n > MAXN) n = MAXN;    // defensive: scratch bound (no-op for this shape)

    int threads = 256;                       // 8 warps = 8 nodes per block
    int blocks  = (n * 32 + threads - 1) / threads;

    norm_kernel<<<blocks, threads>>>(x, n);
    agnn_kernel<<<blocks, threads>>>(x, row_ptr, col_id, beta, out, n);
}